// round 12
// baseline (speedup 1.0000x reference)
#include <cuda_runtime.h>
#include <math.h>

#define S     610
#define SP    640          // padded state dim
#define E     126
#define BATCH 32
#define TLEN  2048
#define NREG  5000
#define JG    20           // column groups (20*32 = 640)
#define BG    4            // batch groups (4*8 = 32)
#define BMP   127          // Bm smem row stride (odd -> conflict-free gather)
#define S0F   0.0079f      // fixed scale anchor

typedef unsigned long long ull;

// ---------------- persistent device scratch ----------------
__device__ float  g_alpha[4][BATCH][SP];   // 4-deep ring, 2 LSBs of each float = epoch tag
__device__ float  g_p[TLEN][BATCH][JG];    // per-step per-colgroup partial sums (strictly > 0)
__device__ double g_part[84];              // finalize partials
__device__ int    g_obsT[TLEN * BATCH];    // obs transposed [t][b]

// ---------------- helpers ----------------
__device__ __forceinline__ float warp_sum(float v) {
    v += __shfl_xor_sync(0xffffffffu, v, 16);
    v += __shfl_xor_sync(0xffffffffu, v, 8);
    v += __shfl_xor_sync(0xffffffffu, v, 4);
    v += __shfl_xor_sync(0xffffffffu, v, 2);
    v += __shfl_xor_sync(0xffffffffu, v, 1);
    return v;
}
__device__ __forceinline__ ull ffma2(ull a, ull b, ull c) {
    ull d;
    asm("fma.rn.f32x2 %0, %1, %2, %3;" : "=l"(d) : "l"(a), "l"(b), "l"(c));
    return d;
}
__device__ __forceinline__ ull packf2(float lo, float hi) {
    ull r;
    asm("mov.b64 %0, {%1, %2};" : "=l"(r) : "f"(lo), "f"(hi));
    return r;
}
__device__ __forceinline__ float ld_cg_f32(const float* p) {
    float v;
    asm volatile("ld.global.cg.f32 %0, [%1];" : "=f"(v) : "l"(p));
    return v;
}
__device__ __forceinline__ void st_cg_f32(float* p, float v) {
    asm volatile("st.global.cg.f32 [%0], %1;" :: "l"(p), "f"(v));
}
__device__ __forceinline__ void cp_async16(unsigned sa, const void* ga) {
    asm volatile("cp.async.cg.shared.global [%0], [%1], 16;" :: "r"(sa), "l"(ga) : "memory");
}
__device__ __forceinline__ void cp_commit() {
    asm volatile("cp.async.commit_group;" ::: "memory");
}
__device__ __forceinline__ void cp_wait1() {
    asm volatile("cp.async.wait_group 1;" ::: "memory");
}
__device__ __forceinline__ void cp_wait0() {
    asm volatile("cp.async.wait_group 0;" ::: "memory");
}
__device__ __forceinline__ bool tags_ok(uint4 u, unsigned tag) {
    return ((u.x & 3u) == tag) & ((u.y & 3u) == tag)
         & ((u.z & 3u) == tag) & ((u.w & 3u) == tag);
}
// stage one warp's 80x16B alpha slice for one chain
__device__ __forceinline__ void issue_slice(unsigned sa_base, int ring, int bbase,
                                            int k0w, int w, int lane) {
#pragma unroll
    for (int j = 0; j < 3; j++) {
        int idx = j * 32 + lane;
        if (j < 2 || lane < 16) {
            int bb = idx / 20, q = idx - bb * 20;
            cp_async16(sa_base + (unsigned)(w * 80 + idx) * 16u,
                       &g_alpha[ring][bbase + bb][k0w + 4 * q]);
        }
    }
}

// ---------------- kernel 1: arm the alpha ring with tag-3 denormals ----------------
__global__ void reset_kernel() {
    int i = blockIdx.x * 256 + threadIdx.x;
    unsigned* p = (unsigned*)g_alpha;
#pragma unroll
    for (int k = 0; k < 4; k++) p[i + k * 80 * 256] = 3u;
}

// nop: shifts ncu's capture slot onto hmm_kernel
__global__ void nop_kernel() {}

// ---------------- kernel 2: one-hot -> index (transposed) ----------------
__global__ void obs_kernel(const float* __restrict__ inputs) {
    int wid = threadIdx.x >> 5, lane = threadIdx.x & 31;
    int idx = blockIdx.x * 8 + wid;             // one warp per (b,t) row
    if (idx >= BATCH * TLEN) return;
    const float* row = inputs + (size_t)idx * E;
    int best = 0;
#pragma unroll
    for (int m = 0; m < 4; m++) {
        int e = lane + 32 * m;
        if (e < E && row[e] > 0.5f) best = e;
    }
#pragma unroll
    for (int d = 16; d; d >>= 1)
        best = max(best, __shfl_xor_sync(0xffffffffu, best, d));
    if (lane == 0) {
        int b = idx / TLEN, t = idx % TLEN;
        g_obsT[t * BATCH + b] = best;
    }
}

// ---------------- kernel 3: persistent scaled forward, 2 interleaved chains ----------------
// grid (20, 4), 256 threads. Chain A = batches bg*8+0..3, chain B = bg*8+4..7.
// Warp w: k-slice [80w, 80w+80) for both chains; owns output batch bg*8+w.
// smem: alsA @0 (10240), alsB @10240 (10240), paccA @20480 (8192),
//       paccB @28672 (8192), Bms @36864 (16256)  -> 53120 B
#define SM_BYTES 53120

__global__ void __launch_bounds__(256, 1)
hmm_kernel(const float* __restrict__ Ag, const float* __restrict__ Bmg,
           const float* __restrict__ Ig) {
    extern __shared__ char sm[];
    ulonglong2* alsA  = (ulonglong2*)(sm);
    ulonglong2* alsB  = (ulonglong2*)(sm + 10240);
    float2*     paccA = (float2*)(sm + 20480);
    float2*     paccB = (float2*)(sm + 28672);
    float*      Bms   = (float*)(sm + 36864);

    const int tid  = threadIdx.x;
    const int w    = tid >> 5, lane = tid & 31;
    const int jg   = blockIdx.x;        // 0..19
    const int bg   = blockIdx.y;        // 0..3
    const int col0 = jg * 32;
    const int col  = col0 + lane;
    const int k0w  = 80 * w;            // this warp's k-slice base
    const int myb  = bg * 8 + w;        // owned output batch

    const unsigned saA = (unsigned)__cvta_generic_to_shared(alsA);
    const unsigned saB = (unsigned)__cvta_generic_to_shared(alsB);

    // ---- prologue: A k-slice x col into registers (zero-padded) ----
    ull au[40];
#pragma unroll
    for (int q = 0; q < 20; q++) {
        int k0 = k0w + 4 * q;
        float x0 = 0.f, x1 = 0.f, x2 = 0.f, x3 = 0.f;
        if (col < S) {
            if (k0     < S) x0 = Ag[(size_t)(k0    ) * S + col];
            if (k0 + 1 < S) x1 = Ag[(size_t)(k0 + 1) * S + col];
            if (k0 + 2 < S) x2 = Ag[(size_t)(k0 + 2) * S + col];
            if (k0 + 3 < S) x3 = Ag[(size_t)(k0 + 3) * S + col];
        }
        au[2 * q]     = packf2(x0, x1);
        au[2 * q + 1] = packf2(x2, x3);
    }
    for (int idx = tid; idx < 32 * BMP; idx += 256) {
        int j = idx / BMP, e = idx % BMP;
        int c = col0 + j;
        Bms[idx] = (c < S && e < E) ? Bmg[(size_t)c * E + e] : 0.f;
    }
    __syncthreads();

    // ---- t = 0: alpha0 = I * em0, tag 0; zp partial ----
    {
        int o = g_obsT[0 * BATCH + myb];
        float iv = (col < S) ? Ig[col] : 0.f;
        float v0 = iv * Bms[lane * BMP + o];
        float vt = __uint_as_float(__float_as_uint(v0) & ~3u);
        st_cg_f32(&g_alpha[0][myb][col], vt);
        float zp = warp_sum(vt);
        if (lane == 0) st_cg_f32(&g_p[0][myb][jg], zp);
    }

    // ---- prime: stage A(1) then B(1) ----
    issue_slice(saA, 0, bg * 8 + 0, k0w, w, lane); cp_commit();
    issue_slice(saB, 0, bg * 8 + 4, k0w, w, lane); cp_commit();

    // one phase of one chain. CHAIN: 0=A, 1=B.
#define PHASE(ALS, SA, PACC, CHAIN)                                            \
    do {                                                                       \
        const int prevr = (t - 1) & 3, curr = t & 3;                           \
        const unsigned tag_r = (unsigned)((t - 1) >> 2) & 3u;                  \
        const unsigned tag_w = (unsigned)(t >> 2) & 3u;                        \
        const int bbase = bg * 8 + (CHAIN) * 4;                                \
        const int ow = w - (CHAIN) * 4;                                        \
        const bool owner = ((unsigned)ow < 4u);                                \
        const int ob = bbase + (owner ? ow : 0);                               \
        float pre = 1.f;                                                       \
        const float* gp = &g_p[(t >= 2 ? t - 2 : 0)][ob][lane];                \
        if (owner && t >= 2 && lane < 20) pre = ld_cg_f32(gp);                 \
        int o = owner ? g_obsT[t * BATCH + ob] : 0;                            \
        /* wait + tag-validate this chain's staged slice */                    \
        cp_wait1();                                                            \
        for (;;) {                                                             \
            __syncwarp();                                                      \
            bool ok = true;                                                    \
            uint4 u0 = ((const uint4*)(ALS))[w * 80 + lane];                   \
            uint4 u1 = ((const uint4*)(ALS))[w * 80 + 32 + lane];              \
            ok &= tags_ok(u0, tag_r) & tags_ok(u1, tag_r);                     \
            if (lane < 16) {                                                   \
                uint4 u2 = ((const uint4*)(ALS))[w * 80 + 64 + lane];          \
                ok &= tags_ok(u2, tag_r);                                      \
            }                                                                  \
            if (__all_sync(0xffffffffu, ok)) break;                            \
            issue_slice(SA, prevr, bbase, k0w, w, lane);                       \
            cp_commit(); cp_wait0();                                           \
        }                                                                      \
        __syncwarp();                                                          \
        /* k-slice matvec: A in registers, alpha via smem broadcast */         \
        ull a0 = 0ull, a1 = 0ull, a2 = 0ull, a3 = 0ull;                        \
        _Pragma("unroll")                                                      \
        for (int q = 0; q < 20; q++) {                                         \
            ulonglong2 v0 = (ALS)[w * 80 +  0 + q];                            \
            ulonglong2 v1 = (ALS)[w * 80 + 20 + q];                            \
            ulonglong2 v2 = (ALS)[w * 80 + 40 + q];                            \
            ulonglong2 v3 = (ALS)[w * 80 + 60 + q];                            \
            a0 = ffma2(v0.x, au[2 * q], a0); a0 = ffma2(v0.y, au[2 * q + 1], a0); \
            a1 = ffma2(v1.x, au[2 * q], a1); a1 = ffma2(v1.y, au[2 * q + 1], a1); \
            a2 = ffma2(v2.x, au[2 * q], a2); a2 = ffma2(v2.y, au[2 * q + 1], a2); \
            a3 = ffma2(v3.x, au[2 * q], a3); a3 = ffma2(v3.y, au[2 * q + 1], a3); \
        }                                                                      \
        float2 f0, f1, f2, f3;                                                 \
        asm("mov.b64 {%0, %1}, %2;" : "=f"(f0.x), "=f"(f0.y) : "l"(a0));       \
        asm("mov.b64 {%0, %1}, %2;" : "=f"(f1.x), "=f"(f1.y) : "l"(a1));       \
        asm("mov.b64 {%0, %1}, %2;" : "=f"(f2.x), "=f"(f2.y) : "l"(a2));       \
        asm("mov.b64 {%0, %1}, %2;" : "=f"(f3.x), "=f"(f3.y) : "l"(a3));       \
        (PACC)[(w * 4 + 0) * 32 + lane] = f0;                                  \
        (PACC)[(w * 4 + 1) * 32 + lane] = f1;                                  \
        (PACC)[(w * 4 + 2) * 32 + lane] = f2;                                  \
        (PACC)[(w * 4 + 3) * 32 + lane] = f3;                                  \
        __syncthreads();                                                       \
        if (owner) {                                                           \
            float ssum = 0.f;                                                  \
            _Pragma("unroll")                                                  \
            for (int w2 = 0; w2 < 8; w2++) {                                   \
                float2 pp = (PACC)[(w2 * 4 + ow) * 32 + lane];                 \
                ssum += pp.x + pp.y;                                           \
            }                                                                  \
            float rz = 1.f;                                                    \
            if (t >= 2) {                                                      \
                for (;;) {                                                     \
                    if (__all_sync(0xffffffffu, (lane >= 20) | (pre != 0.f))) break; \
                    if (lane < 20) pre = ld_cg_f32(gp);                        \
                }                                                              \
                rz = rsqrtf(warp_sum(lane < 20 ? pre : 0.f) * S0F);            \
            }                                                                  \
            float val = ssum * Bms[lane * BMP + o] * rz;                       \
            float vt = __uint_as_float((__float_as_uint(val) & ~3u) | tag_w);  \
            st_cg_f32(&g_alpha[curr][ob][col], vt);                            \
            float zp = warp_sum(vt);                                           \
            if (lane == 0) st_cg_f32(&g_p[t][ob][jg], zp);                     \
        }                                                                      \
        /* stage this chain's slice for step t+1 */                            \
        issue_slice(SA, curr, bbase, k0w, w, lane);                            \
        cp_commit();                                                           \
    } while (0)

    for (int t = 1; t < TLEN; ++t) {
        PHASE(alsA, saA, paccA, 0);
        PHASE(alsB, saB, paccB, 1);
    }
#undef PHASE
}

// ---------------- kernel 4a: parallel loglik + regularizer partials ----------------
__global__ void finalize1_kernel(const float* __restrict__ Ag,
                                 const int* __restrict__ rf,
                                 const int* __restrict__ rt) {
    __shared__ double red[256];
    int blk = blockIdx.x, tid = threadIdx.x;
    double acc = 0.0;
    if (blk < 64) {
        int b = blk & 31, t0 = (blk >> 5) * 1024;
        for (int i = tid; i < 1024; i += 256) {
            int t = t0 + i;
            const float4* row = (const float4*)&g_p[t][b][0];  // 20 floats, 16B-aligned
            float4 r0 = row[0], r1 = row[1], r2 = row[2], r3 = row[3], r4 = row[4];
            float s = ((r0.x + r0.y) + (r0.z + r0.w)) + ((r1.x + r1.y) + (r1.z + r1.w))
                    + ((r2.x + r2.y) + (r2.z + r2.w)) + ((r3.x + r3.y) + (r3.z + r3.w))
                    + ((r4.x + r4.y) + (r4.z + r4.w));
            if (t <= TLEN - 3) {
                acc -= (double)logf(rsqrtf(s * S0F));  // divisor applied at step t+2
            } else if (t == TLEN - 1) {
                acc += (double)logf(s);
            }
        }
    } else {
        int idx = (blk - 64) * 256 + tid;
        if (idx < NREG) {
            float a = Ag[(size_t)rf[idx] * S + rt[idx]];
            acc = (double)log1pf(-a);
        }
    }
    red[tid] = acc;
    __syncthreads();
    for (int st = 128; st; st >>= 1) {
        if (tid < st) red[tid] += red[tid + st];
        __syncthreads();
    }
    if (tid == 0) g_part[blk] = red[0];
}

// ---------------- kernel 4b: combine ----------------
__global__ void finalize2_kernel(float* __restrict__ out) {
    if (threadIdx.x == 0) {
        double ll = 0.0, rg = 0.0;
        for (int i = 0; i < 64; i++) ll += g_part[i];
        for (int i = 64; i < 84; i++) rg += g_part[i];
        double loss = -(ll / (double)BATCH) - 4.0 * (rg / (double)NREG);
        out[0] = (float)loss;
    }
}

// ---------------- launcher ----------------
extern "C" void kernel_launch(void* const* d_in, const int* in_sizes, int n_in,
                              void* d_out, int out_size) {
    const float* inputs = (const float*)d_in[0];   // [32,2048,126]
    const float* A      = (const float*)d_in[1];   // [610,610]
    const float* Bm     = (const float*)d_in[2];   // [610,126]
    const float* I      = (const float*)d_in[3];   // [610]
    const int*   rf     = (const int*)d_in[4];     // [5000]
    const int*   rt     = (const int*)d_in[5];     // [5000]
    float* out = (float*)d_out;

    cudaFuncSetAttribute(hmm_kernel,
                         cudaFuncAttributeMaxDynamicSharedMemorySize, SM_BYTES);

    reset_kernel<<<80, 256>>>();
    obs_kernel<<<(BATCH * TLEN) / 8, 256>>>(inputs);
    nop_kernel<<<1, 32>>>();
    dim3 grid(JG, BG);
    hmm_kernel<<<grid, 256, SM_BYTES>>>(A, Bm, I);
    finalize1_kernel<<<84, 256>>>(A, rf, rt);
    finalize2_kernel<<<1, 32>>>(out);
}

// round 13
// speedup vs baseline: 1.0823x; 1.0823x over previous
#include <cuda_runtime.h>
#include <math.h>

#define S     610
#define SP    640          // padded state dim
#define E     126
#define BATCH 32
#define TLEN  2048
#define NREG  5000
#define JG    20           // column groups (20*32 = 640)
#define BG    4            // batch groups (4*8 = 32)
#define NB    8            // batches per block
#define BMP   127          // Bm smem row stride (odd -> conflict-free gather)
#define S0F   0.0079f      // fixed scale anchor

typedef unsigned long long ull;

// ---------------- persistent device scratch ----------------
__device__ float  g_alpha[4][BATCH][SP];   // 4-deep ring, 2 LSBs of each float = epoch tag
__device__ float  g_p[TLEN][BATCH][JG];    // per-step per-colgroup partial sums (strictly > 0)
__device__ double g_part[84];              // finalize partials
__device__ int    g_obsT[TLEN * BATCH];    // obs transposed [t][b]

// ---------------- helpers ----------------
__device__ __forceinline__ float warp_sum(float v) {
    v += __shfl_xor_sync(0xffffffffu, v, 16);
    v += __shfl_xor_sync(0xffffffffu, v, 8);
    v += __shfl_xor_sync(0xffffffffu, v, 4);
    v += __shfl_xor_sync(0xffffffffu, v, 2);
    v += __shfl_xor_sync(0xffffffffu, v, 1);
    return v;
}
__device__ __forceinline__ ull ffma2(ull a, ull b, ull c) {
    ull d;
    asm("fma.rn.f32x2 %0, %1, %2, %3;" : "=l"(d) : "l"(a), "l"(b), "l"(c));
    return d;
}
__device__ __forceinline__ ull packf2(float lo, float hi) {
    ull r;
    asm("mov.b64 %0, {%1, %2};" : "=l"(r) : "f"(lo), "f"(hi));
    return r;
}
__device__ __forceinline__ float ld_cg_f32(const float* p) {
    float v;
    asm volatile("ld.global.cg.f32 %0, [%1];" : "=f"(v) : "l"(p));
    return v;
}
__device__ __forceinline__ void st_cg_f32(float* p, float v) {
    asm volatile("st.global.cg.f32 [%0], %1;" :: "l"(p), "f"(v));
}
__device__ __forceinline__ void cp_async16(unsigned sa, const void* ga) {
    asm volatile("cp.async.cg.shared.global [%0], [%1], 16;" :: "r"(sa), "l"(ga) : "memory");
}
__device__ __forceinline__ void cp_commit() {
    asm volatile("cp.async.commit_group;" ::: "memory");
}
__device__ __forceinline__ void cp_wait1() {
    asm volatile("cp.async.wait_group 1;" ::: "memory");
}
__device__ __forceinline__ void cp_wait0() {
    asm volatile("cp.async.wait_group 0;" ::: "memory");
}
__device__ __forceinline__ bool tags_ok(uint4 u, unsigned tag) {
    return ((u.x & 3u) == tag) & ((u.y & 3u) == tag)
         & ((u.z & 3u) == tag) & ((u.w & 3u) == tag);
}

// ---------------- kernel 1: arm the alpha ring with tag-3 denormals ----------------
__global__ void reset_kernel() {
    int i = blockIdx.x * 256 + threadIdx.x;
    unsigned* p = (unsigned*)g_alpha;
#pragma unroll
    for (int k = 0; k < 4; k++) p[i + k * 80 * 256] = 3u;
}

// nop: keeps ncu's capture slot on hmm_kernel
__global__ void nop_kernel() {}

// ---------------- kernel 2: one-hot -> index (transposed) ----------------
__global__ void obs_kernel(const float* __restrict__ inputs) {
    int wid = threadIdx.x >> 5, lane = threadIdx.x & 31;
    int idx = blockIdx.x * 8 + wid;             // one warp per (b,t) row
    if (idx >= BATCH * TLEN) return;
    const float* row = inputs + (size_t)idx * E;
    int best = 0;
#pragma unroll
    for (int m = 0; m < 4; m++) {
        int e = lane + 32 * m;
        if (e < E && row[e] > 0.5f) best = e;
    }
#pragma unroll
    for (int d = 16; d; d >>= 1)
        best = max(best, __shfl_xor_sync(0xffffffffu, best, d));
    if (lane == 0) {
        int b = idx / TLEN, t = idx % TLEN;
        g_obsT[t * BATCH + b] = best;
    }
}

// ---------------- kernel 3: persistent scaled forward, split-half staging ----------------
// grid (20, 4), 256 threads. Warp w: output batch bg*8+w; compute k-slice [80w, 80w+80).
// A slice in registers (40 ull). smem:
//   als      ulonglong2[8*160] @     0  (20480)  alpha_{t-1} slices [w][bb*20+q]
//   pacc[2]  float2[8*8*32]    @ 20480 / 36864   k-partials [w][bb][lane], parity-buffered
//   Bms      float[32*127]     @ 53248  (16256)
#define SM_BYTES 69504

__global__ void __launch_bounds__(256, 1)
hmm_kernel(const float* __restrict__ Ag, const float* __restrict__ Bmg,
           const float* __restrict__ Ig) {
    extern __shared__ char sm[];
    ulonglong2* als = (ulonglong2*)(sm);
    float*      Bms = (float*)(sm + 53248);

    const int tid  = threadIdx.x;
    const int w    = tid >> 5, lane = tid & 31;
    const int jg   = blockIdx.x;        // 0..19
    const int bg   = blockIdx.y;        // 0..3
    const int bgb  = bg * NB;           // first batch of this group
    const int b    = bgb + w;           // owned output batch
    const int col0 = jg * 32;
    const int col  = col0 + lane;
    const int k0w  = 80 * w;            // this warp's k-slice base

    const unsigned sa_als = (unsigned)__cvta_generic_to_shared(als);

    // issue one half (4 batches x 20 k-quads = 80 x 16B) of the alpha slice + commit
#define ISSUE_HALF(RING, HALF)                                                 \
    do {                                                                       \
        int i0 = 80 * (HALF) + lane;                                           \
        int bb0 = i0 / 20, q0_ = i0 - bb0 * 20;                                \
        cp_async16(sa_als + (unsigned)(w * 160 + i0) * 16u,                    \
                   &g_alpha[RING][bgb + bb0][k0w + 4 * q0_]);                  \
        int i1 = i0 + 32;                                                      \
        int bb1 = i1 / 20, q1_ = i1 - bb1 * 20;                                \
        cp_async16(sa_als + (unsigned)(w * 160 + i1) * 16u,                    \
                   &g_alpha[RING][bgb + bb1][k0w + 4 * q1_]);                  \
        if (lane < 16) {                                                       \
            int i2 = i0 + 64;                                                  \
            int bb2 = i2 / 20, q2_ = i2 - bb2 * 20;                            \
            cp_async16(sa_als + (unsigned)(w * 160 + i2) * 16u,                \
                       &g_alpha[RING][bgb + bb2][k0w + 4 * q2_]);              \
        }                                                                      \
        cp_commit();                                                           \
    } while (0)

#define CHECK_HALF(HALF, TAGR, OKVAR)                                          \
    do {                                                                       \
        OKVAR = true;                                                          \
        uint4 u0 = ((const uint4*)als)[w * 160 + 80 * (HALF) + lane];          \
        uint4 u1 = ((const uint4*)als)[w * 160 + 80 * (HALF) + 32 + lane];     \
        OKVAR &= tags_ok(u0, TAGR) & tags_ok(u1, TAGR);                        \
        if (lane < 16) {                                                       \
            uint4 u2 = ((const uint4*)als)[w * 160 + 80 * (HALF) + 64 + lane]; \
            OKVAR &= tags_ok(u2, TAGR);                                        \
        }                                                                      \
    } while (0)

    // ---- prologue: A k-slice x col into registers (zero-padded) ----
    ull au[40];
#pragma unroll
    for (int q = 0; q < 20; q++) {
        int k0 = k0w + 4 * q;
        float x0 = 0.f, x1 = 0.f, x2 = 0.f, x3 = 0.f;
        if (col < S) {
            if (k0     < S) x0 = Ag[(size_t)(k0    ) * S + col];
            if (k0 + 1 < S) x1 = Ag[(size_t)(k0 + 1) * S + col];
            if (k0 + 2 < S) x2 = Ag[(size_t)(k0 + 2) * S + col];
            if (k0 + 3 < S) x3 = Ag[(size_t)(k0 + 3) * S + col];
        }
        au[2 * q]     = packf2(x0, x1);
        au[2 * q + 1] = packf2(x2, x3);
    }
    for (int idx = tid; idx < 32 * BMP; idx += 256) {
        int j = idx / BMP, e = idx % BMP;
        int c = col0 + j;
        Bms[idx] = (c < S && e < E) ? Bmg[(size_t)c * E + e] : 0.f;
    }
    __syncthreads();

    // ---- t = 0: alpha0 = I * em0, tag 0; zp partial ----
    {
        int o = g_obsT[0 * BATCH + b];
        float iv = (col < S) ? Ig[col] : 0.f;
        float v0 = iv * Bms[lane * BMP + o];
        float vt = __uint_as_float(__float_as_uint(v0) & ~3u);
        st_cg_f32(&g_alpha[0][b][col], vt);
        float zp = warp_sum(vt);
        if (lane == 0) st_cg_f32(&g_p[0][b][jg], zp);
    }

    // prime staging for t = 1 (ring 0)
    ISSUE_HALF(0, 0);
    ISSUE_HALF(0, 1);

    for (int t = 1; t < TLEN; ++t) {
        const int prevr = (t - 1) & 3, curr = t & 3;
        const unsigned tag_r = (unsigned)((t - 1) >> 2) & 3u;
        const unsigned tag_w = (unsigned)(t >> 2) & 3u;
        float2* pacc = (float2*)(sm + 20480 + (t & 1) * 16384);

        // prefetch scalars (overlap with in-flight copies)
        const float* gp = &g_p[(t >= 2 ? t - 2 : 0)][b][lane];
        float pre = 1.f;
        if (t >= 2 && lane < 20) pre = ld_cg_f32(gp);
        int o = g_obsT[t * BATCH + b];
        float rz = 1.f;
        bool rz_done = (t < 2);

        // ---- validate half 1 (batches bgb..bgb+3); G2 still in flight ----
        cp_wait1();
        for (;;) {
            __syncwarp();
            bool ok;
            CHECK_HALF(0, tag_r, ok);
            if (__all_sync(0xffffffffu, ok)) break;
            ISSUE_HALF(prevr, 0);
            cp_wait0();
        }
        __syncwarp();

        // ---- FMA half 1 (covers G2's arrival) ----
        ull a0 = 0ull, a1 = 0ull, a2 = 0ull, a3 = 0ull;
#pragma unroll
        for (int q = 0; q < 20; q++) {
            ulonglong2 v0 = als[w * 160 +  0 + q];
            ulonglong2 v1 = als[w * 160 + 20 + q];
            ulonglong2 v2 = als[w * 160 + 40 + q];
            ulonglong2 v3 = als[w * 160 + 60 + q];
            a0 = ffma2(v0.x, au[2 * q], a0); a0 = ffma2(v0.y, au[2 * q + 1], a0);
            a1 = ffma2(v1.x, au[2 * q], a1); a1 = ffma2(v1.y, au[2 * q + 1], a1);
            a2 = ffma2(v2.x, au[2 * q], a2); a2 = ffma2(v2.y, au[2 * q + 1], a2);
            a3 = ffma2(v3.x, au[2 * q], a3); a3 = ffma2(v3.y, au[2 * q + 1], a3);
        }

        // rz fast path in the slack before validating half 2
        if (!rz_done) {
            if (__all_sync(0xffffffffu, (lane >= 20) | (pre != 0.f))) {
                rz = rsqrtf(warp_sum(lane < 20 ? pre : 0.f) * S0F);
                rz_done = true;
            }
        }

        // ---- validate half 2 (batches bgb+4..bgb+7) ----
        cp_wait0();
        for (;;) {
            __syncwarp();
            bool ok;
            CHECK_HALF(1, tag_r, ok);
            if (__all_sync(0xffffffffu, ok)) break;
            ISSUE_HALF(prevr, 1);
            cp_wait0();
        }
        __syncwarp();

        // ---- FMA half 2 ----
        ull a4 = 0ull, a5 = 0ull, a6 = 0ull, a7 = 0ull;
#pragma unroll
        for (int q = 0; q < 20; q++) {
            ulonglong2 v4 = als[w * 160 +  80 + q];
            ulonglong2 v5 = als[w * 160 + 100 + q];
            ulonglong2 v6 = als[w * 160 + 120 + q];
            ulonglong2 v7 = als[w * 160 + 140 + q];
            a4 = ffma2(v4.x, au[2 * q], a4); a4 = ffma2(v4.y, au[2 * q + 1], a4);
            a5 = ffma2(v5.x, au[2 * q], a5); a5 = ffma2(v5.y, au[2 * q + 1], a5);
            a6 = ffma2(v6.x, au[2 * q], a6); a6 = ffma2(v6.y, au[2 * q + 1], a6);
            a7 = ffma2(v7.x, au[2 * q], a7); a7 = ffma2(v7.y, au[2 * q + 1], a7);
        }

        // ---- publish k-partials ----
        float2 f;
        asm("mov.b64 {%0, %1}, %2;" : "=f"(f.x), "=f"(f.y) : "l"(a0)); pacc[(w * NB + 0) * 32 + lane] = f;
        asm("mov.b64 {%0, %1}, %2;" : "=f"(f.x), "=f"(f.y) : "l"(a1)); pacc[(w * NB + 1) * 32 + lane] = f;
        asm("mov.b64 {%0, %1}, %2;" : "=f"(f.x), "=f"(f.y) : "l"(a2)); pacc[(w * NB + 2) * 32 + lane] = f;
        asm("mov.b64 {%0, %1}, %2;" : "=f"(f.x), "=f"(f.y) : "l"(a3)); pacc[(w * NB + 3) * 32 + lane] = f;
        asm("mov.b64 {%0, %1}, %2;" : "=f"(f.x), "=f"(f.y) : "l"(a4)); pacc[(w * NB + 4) * 32 + lane] = f;
        asm("mov.b64 {%0, %1}, %2;" : "=f"(f.x), "=f"(f.y) : "l"(a5)); pacc[(w * NB + 5) * 32 + lane] = f;
        asm("mov.b64 {%0, %1}, %2;" : "=f"(f.x), "=f"(f.y) : "l"(a6)); pacc[(w * NB + 6) * 32 + lane] = f;
        asm("mov.b64 {%0, %1}, %2;" : "=f"(f.x), "=f"(f.y) : "l"(a7)); pacc[(w * NB + 7) * 32 + lane] = f;
        __syncthreads();

        // ---- owner tail: reduce, scale, store alpha_t + partial ----
        {
            float ssum = 0.f;
#pragma unroll
            for (int w2 = 0; w2 < 8; w2++) {
                float2 pp = pacc[(w2 * NB + w) * 32 + lane];
                ssum += pp.x + pp.y;
            }
            if (!rz_done) {                 // slow path: s_{t-2} not yet visible
                for (;;) {
                    if (__all_sync(0xffffffffu, (lane >= 20) | (pre != 0.f))) break;
                    if (lane < 20) pre = ld_cg_f32(gp);
                }
                rz = rsqrtf(warp_sum(lane < 20 ? pre : 0.f) * S0F);
            }
            float val = ssum * Bms[lane * BMP + o] * rz;
            float vt = __uint_as_float((__float_as_uint(val) & ~3u) | tag_w);
            st_cg_f32(&g_alpha[curr][b][col], vt);
            float zp = warp_sum(vt);
            if (lane == 0) st_cg_f32(&g_p[t][b][jg], zp);
        }

        // ---- prefetch next step's slices (tags gate staleness) ----
        if (t + 1 < TLEN) {
            ISSUE_HALF(curr, 0);
            ISSUE_HALF(curr, 1);
        }
    }
#undef ISSUE_HALF
#undef CHECK_HALF
}

// ---------------- kernel 4a: parallel loglik + regularizer partials ----------------
__global__ void finalize1_kernel(const float* __restrict__ Ag,
                                 const int* __restrict__ rf,
                                 const int* __restrict__ rt) {
    __shared__ double red[256];
    int blk = blockIdx.x, tid = threadIdx.x;
    double acc = 0.0;
    if (blk < 64) {
        int b = blk & 31, t0 = (blk >> 5) * 1024;
        for (int i = tid; i < 1024; i += 256) {
            int t = t0 + i;
            const float4* row = (const float4*)&g_p[t][b][0];  // 20 floats, 16B-aligned
            float4 r0 = row[0], r1 = row[1], r2 = row[2], r3 = row[3], r4 = row[4];
            float s = ((r0.x + r0.y) + (r0.z + r0.w)) + ((r1.x + r1.y) + (r1.z + r1.w))
                    + ((r2.x + r2.y) + (r2.z + r2.w)) + ((r3.x + r3.y) + (r3.z + r3.w))
                    + ((r4.x + r4.y) + (r4.z + r4.w));
            if (t <= TLEN - 3) {
                acc -= (double)logf(rsqrtf(s * S0F));  // divisor applied at step t+2
            } else if (t == TLEN - 1) {
                acc += (double)logf(s);
            }
        }
    } else {
        int idx = (blk - 64) * 256 + tid;
        if (idx < NREG) {
            float a = Ag[(size_t)rf[idx] * S + rt[idx]];
            acc = (double)log1pf(-a);
        }
    }
    red[tid] = acc;
    __syncthreads();
    for (int st = 128; st; st >>= 1) {
        if (tid < st) red[tid] += red[tid + st];
        __syncthreads();
    }
    if (tid == 0) g_part[blk] = red[0];
}

// ---------------- kernel 4b: combine ----------------
__global__ void finalize2_kernel(float* __restrict__ out) {
    if (threadIdx.x == 0) {
        double ll = 0.0, rg = 0.0;
        for (int i = 0; i < 64; i++) ll += g_part[i];
        for (int i = 64; i < 84; i++) rg += g_part[i];
        double loss = -(ll / (double)BATCH) - 4.0 * (rg / (double)NREG);
        out[0] = (float)loss;
    }
}

// ---------------- launcher ----------------
extern "C" void kernel_launch(void* const* d_in, const int* in_sizes, int n_in,
                              void* d_out, int out_size) {
    const float* inputs = (const float*)d_in[0];   // [32,2048,126]
    const float* A      = (const float*)d_in[1];   // [610,610]
    const float* Bm     = (const float*)d_in[2];   // [610,126]
    const float* I      = (const float*)d_in[3];   // [610]
    const int*   rf     = (const int*)d_in[4];     // [5000]
    const int*   rt     = (const int*)d_in[5];     // [5000]
    float* out = (float*)d_out;

    cudaFuncSetAttribute(hmm_kernel,
                         cudaFuncAttributeMaxDynamicSharedMemorySize, SM_BYTES);

    reset_kernel<<<80, 256>>>();
    obs_kernel<<<(BATCH * TLEN) / 8, 256>>>(inputs);
    nop_kernel<<<1, 32>>>();
    dim3 grid(JG, BG);
    hmm_kernel<<<grid, 256, SM_BYTES>>>(A, Bm, I);
    finalize1_kernel<<<84, 256>>>(A, rf, rt);
    finalize2_kernel<<<1, 32>>>(out);
}

// round 14
// speedup vs baseline: 1.1911x; 1.1005x over previous
#include <cuda_runtime.h>
#include <math.h>

#define S     610
#define SP    640          // padded state dim
#define E     126
#define BATCH 32
#define TLEN  2048
#define NREG  5000
#define JG    20           // column groups (20*32 = 640)
#define BG    4            // batch groups (4*8 = 32)
#define NB    8            // batches per block
#define NW    16           // warps per block
#define BMP   127          // Bm smem row stride (odd -> conflict-free gather)
#define S0F   0.0079f      // fixed scale anchor

typedef unsigned long long ull;

// ---------------- persistent device scratch ----------------
__device__ float  g_alpha[4][BATCH][SP];   // 4-deep ring, 2 LSBs of each float = epoch tag
__device__ float  g_p[TLEN][BATCH][JG];    // per-step per-colgroup partial sums (strictly > 0)
__device__ double g_part[84];              // finalize partials
__device__ int    g_obsT[TLEN * BATCH];    // obs transposed [t][b]

// ---------------- helpers ----------------
__device__ __forceinline__ float warp_sum(float v) {
    v += __shfl_xor_sync(0xffffffffu, v, 16);
    v += __shfl_xor_sync(0xffffffffu, v, 8);
    v += __shfl_xor_sync(0xffffffffu, v, 4);
    v += __shfl_xor_sync(0xffffffffu, v, 2);
    v += __shfl_xor_sync(0xffffffffu, v, 1);
    return v;
}
__device__ __forceinline__ ull ffma2(ull a, ull b, ull c) {
    ull d;
    asm("fma.rn.f32x2 %0, %1, %2, %3;" : "=l"(d) : "l"(a), "l"(b), "l"(c));
    return d;
}
__device__ __forceinline__ ull packf2(float lo, float hi) {
    ull r;
    asm("mov.b64 %0, {%1, %2};" : "=l"(r) : "f"(lo), "f"(hi));
    return r;
}
__device__ __forceinline__ float ld_cg_f32(const float* p) {
    float v;
    asm volatile("ld.global.cg.f32 %0, [%1];" : "=f"(v) : "l"(p));
    return v;
}
__device__ __forceinline__ void st_cg_f32(float* p, float v) {
    asm volatile("st.global.cg.f32 [%0], %1;" :: "l"(p), "f"(v));
}
__device__ __forceinline__ void cp_async16(unsigned sa, const void* ga) {
    asm volatile("cp.async.cg.shared.global [%0], [%1], 16;" :: "r"(sa), "l"(ga) : "memory");
}
__device__ __forceinline__ void cp_commit() {
    asm volatile("cp.async.commit_group;" ::: "memory");
}
__device__ __forceinline__ void cp_wait0() {
    asm volatile("cp.async.wait_group 0;" ::: "memory");
}
__device__ __forceinline__ bool tags_ok(uint4 u, unsigned tag) {
    return ((u.x & 3u) == tag) & ((u.y & 3u) == tag)
         & ((u.z & 3u) == tag) & ((u.w & 3u) == tag);
}

// ---------------- kernel 1: arm the alpha ring with tag-3 denormals ----------------
__global__ void reset_kernel() {
    int i = blockIdx.x * 256 + threadIdx.x;
    unsigned* p = (unsigned*)g_alpha;
#pragma unroll
    for (int k = 0; k < 4; k++) p[i + k * 80 * 256] = 3u;
}

// nop: keeps ncu's capture slot on hmm_kernel
__global__ void nop_kernel() {}

// ---------------- kernel 2: one-hot -> index (transposed) ----------------
__global__ void obs_kernel(const float* __restrict__ inputs) {
    int wid = threadIdx.x >> 5, lane = threadIdx.x & 31;
    int idx = blockIdx.x * 8 + wid;             // one warp per (b,t) row
    if (idx >= BATCH * TLEN) return;
    const float* row = inputs + (size_t)idx * E;
    int best = 0;
#pragma unroll
    for (int m = 0; m < 4; m++) {
        int e = lane + 32 * m;
        if (e < E && row[e] > 0.5f) best = e;
    }
#pragma unroll
    for (int d = 16; d; d >>= 1)
        best = max(best, __shfl_xor_sync(0xffffffffu, best, d));
    if (lane == 0) {
        int b = idx / TLEN, t = idx % TLEN;
        g_obsT[t * BATCH + b] = best;
    }
}

// ---------------- kernel 3: persistent scaled forward, 16 warps ----------------
// grid (20, 4), 512 threads. Warp w (0..15): compute k-slice [40w, 40w+40) for all
// 8 batches; warps 0..7 additionally own output batch bg*8+w.
// A slice in registers (20 ull / thread). smem:
//   als      ulonglong2[16*80] @     0  (20480)  alpha_{t-1} slices [w][bb*10+q]
//   pacc[2]  float2[16*8*32]   @ 20480 / 53248   k-partials [w][bb][lane], parity-buffered
//   Bms      float[32*127]     @ 86016  (16256)
#define SM_BYTES 102272

__global__ void __launch_bounds__(512, 1)
hmm_kernel(const float* __restrict__ Ag, const float* __restrict__ Bmg,
           const float* __restrict__ Ig) {
    extern __shared__ char sm[];
    ulonglong2* als = (ulonglong2*)(sm);
    float*      Bms = (float*)(sm + 86016);

    const int tid  = threadIdx.x;
    const int w    = tid >> 5, lane = tid & 31;
    const int jg   = blockIdx.x;        // 0..19
    const int bg   = blockIdx.y;        // 0..3
    const int bgb  = bg * NB;           // first batch of this group
    const bool owner = (w < NB);
    const int b    = bgb + (owner ? w : 0);  // owned output batch (owners only)
    const int col0 = jg * 32;
    const int col  = col0 + lane;
    const int k0w  = 40 * w;            // this warp's k-slice base

    const unsigned sa_als = (unsigned)__cvta_generic_to_shared(als);

    // chunk index -> (bb, q): i in [0,80), bb = i/10, q = i%10
    const int i0 = lane,      bb0 = i0 / 10, q0c = i0 - bb0 * 10;
    const int i1 = lane + 32, bb1 = i1 / 10, q1c = i1 - bb1 * 10;
    const int i2 = lane + 64, bb2 = i2 / 10, q2c = i2 - bb2 * 10;   // valid if lane<16

#define ISSUE_SLICE(RING)                                                      \
    do {                                                                       \
        cp_async16(sa_als + (unsigned)(w * 80 + i0) * 16u,                     \
                   &g_alpha[RING][bgb + bb0][k0w + 4 * q0c]);                  \
        cp_async16(sa_als + (unsigned)(w * 80 + i1) * 16u,                     \
                   &g_alpha[RING][bgb + bb1][k0w + 4 * q1c]);                  \
        if (lane < 16)                                                         \
            cp_async16(sa_als + (unsigned)(w * 80 + i2) * 16u,                 \
                       &g_alpha[RING][bgb + bb2][k0w + 4 * q2c]);              \
        cp_commit();                                                           \
    } while (0)

    // ---- prologue: A k-slice x col into registers (zero-padded) ----
    ull au[20];
#pragma unroll
    for (int q = 0; q < 10; q++) {
        int k0 = k0w + 4 * q;
        float x0 = 0.f, x1 = 0.f, x2 = 0.f, x3 = 0.f;
        if (col < S) {
            if (k0     < S) x0 = Ag[(size_t)(k0    ) * S + col];
            if (k0 + 1 < S) x1 = Ag[(size_t)(k0 + 1) * S + col];
            if (k0 + 2 < S) x2 = Ag[(size_t)(k0 + 2) * S + col];
            if (k0 + 3 < S) x3 = Ag[(size_t)(k0 + 3) * S + col];
        }
        au[2 * q]     = packf2(x0, x1);
        au[2 * q + 1] = packf2(x2, x3);
    }
    for (int idx = tid; idx < 32 * BMP; idx += 512) {
        int j = idx / BMP, e = idx % BMP;
        int c = col0 + j;
        Bms[idx] = (c < S && e < E) ? Bmg[(size_t)c * E + e] : 0.f;
    }
    __syncthreads();

    // ---- t = 0: alpha0 = I * em0, tag 0; zp partial (owners only) ----
    if (owner) {
        int o = g_obsT[0 * BATCH + b];
        float iv = (col < S) ? Ig[col] : 0.f;
        float v0 = iv * Bms[lane * BMP + o];
        float vt = __uint_as_float(__float_as_uint(v0) & ~3u);
        st_cg_f32(&g_alpha[0][b][col], vt);
        float zp = warp_sum(vt);
        if (lane == 0) st_cg_f32(&g_p[0][b][jg], zp);
    }
    __syncthreads();

    // prime staging for t = 1 (ring 0)
    ISSUE_SLICE(0);

    for (int t = 1; t < TLEN; ++t) {
        const int prevr = (t - 1) & 3, curr = t & 3;
        const unsigned tag_r = (unsigned)((t - 1) >> 2) & 3u;
        const unsigned tag_w = (unsigned)(t >> 2) & 3u;
        float2* pacc = (float2*)(sm + 20480 + (t & 1) * 32768);

        // prefetch scalars (overlap with in-flight copies)
        float pre = 1.f;
        const float* gp = &g_p[(t >= 2 ? t - 2 : 0)][b][lane];
        int o = 0;
        if (owner) {
            if (t >= 2 && lane < 20) pre = ld_cg_f32(gp);
            o = g_obsT[t * BATCH + b];
        }
        float rz = 1.f;
        bool rz_done = (!owner) || (t < 2);

        // ---- wait + tag-validate staged alpha; retry until fresh ----
        for (;;) {
            cp_wait0();
            __syncwarp();
            bool ok = true;
            uint4 u0 = ((const uint4*)als)[w * 80 + i0];
            uint4 u1 = ((const uint4*)als)[w * 80 + i1];
            ok &= tags_ok(u0, tag_r) & tags_ok(u1, tag_r);
            if (lane < 16) {
                uint4 u2 = ((const uint4*)als)[w * 80 + i2];
                ok &= tags_ok(u2, tag_r);
            }
            if (__all_sync(0xffffffffu, ok)) break;
            ISSUE_SLICE(prevr);
        }
        __syncwarp();

        // rz fast path in the slack after validate
        if (!rz_done) {
            if (__all_sync(0xffffffffu, (lane >= 20) | (pre != 0.f))) {
                rz = rsqrtf(warp_sum(lane < 20 ? pre : 0.f) * S0F);
                rz_done = true;
            }
        }

        // ---- k-slice matvec: A in registers, alpha via smem broadcast ----
        ull a0 = 0ull, a1 = 0ull, a2 = 0ull, a3 = 0ull;
        ull a4 = 0ull, a5 = 0ull, a6 = 0ull, a7 = 0ull;
#pragma unroll
        for (int q = 0; q < 10; q++) {
            ulonglong2 v0 = als[w * 80 +  0 + q];
            ulonglong2 v1 = als[w * 80 + 10 + q];
            ulonglong2 v2 = als[w * 80 + 20 + q];
            ulonglong2 v3 = als[w * 80 + 30 + q];
            a0 = ffma2(v0.x, au[2 * q], a0); a0 = ffma2(v0.y, au[2 * q + 1], a0);
            a1 = ffma2(v1.x, au[2 * q], a1); a1 = ffma2(v1.y, au[2 * q + 1], a1);
            a2 = ffma2(v2.x, au[2 * q], a2); a2 = ffma2(v2.y, au[2 * q + 1], a2);
            a3 = ffma2(v3.x, au[2 * q], a3); a3 = ffma2(v3.y, au[2 * q + 1], a3);
            ulonglong2 v4 = als[w * 80 + 40 + q];
            ulonglong2 v5 = als[w * 80 + 50 + q];
            ulonglong2 v6 = als[w * 80 + 60 + q];
            ulonglong2 v7 = als[w * 80 + 70 + q];
            a4 = ffma2(v4.x, au[2 * q], a4); a4 = ffma2(v4.y, au[2 * q + 1], a4);
            a5 = ffma2(v5.x, au[2 * q], a5); a5 = ffma2(v5.y, au[2 * q + 1], a5);
            a6 = ffma2(v6.x, au[2 * q], a6); a6 = ffma2(v6.y, au[2 * q + 1], a6);
            a7 = ffma2(v7.x, au[2 * q], a7); a7 = ffma2(v7.y, au[2 * q + 1], a7);
        }

        // ---- publish k-partials ----
        float2 f;
        asm("mov.b64 {%0, %1}, %2;" : "=f"(f.x), "=f"(f.y) : "l"(a0)); pacc[(w * NB + 0) * 32 + lane] = f;
        asm("mov.b64 {%0, %1}, %2;" : "=f"(f.x), "=f"(f.y) : "l"(a1)); pacc[(w * NB + 1) * 32 + lane] = f;
        asm("mov.b64 {%0, %1}, %2;" : "=f"(f.x), "=f"(f.y) : "l"(a2)); pacc[(w * NB + 2) * 32 + lane] = f;
        asm("mov.b64 {%0, %1}, %2;" : "=f"(f.x), "=f"(f.y) : "l"(a3)); pacc[(w * NB + 3) * 32 + lane] = f;
        asm("mov.b64 {%0, %1}, %2;" : "=f"(f.x), "=f"(f.y) : "l"(a4)); pacc[(w * NB + 4) * 32 + lane] = f;
        asm("mov.b64 {%0, %1}, %2;" : "=f"(f.x), "=f"(f.y) : "l"(a5)); pacc[(w * NB + 5) * 32 + lane] = f;
        asm("mov.b64 {%0, %1}, %2;" : "=f"(f.x), "=f"(f.y) : "l"(a6)); pacc[(w * NB + 6) * 32 + lane] = f;
        asm("mov.b64 {%0, %1}, %2;" : "=f"(f.x), "=f"(f.y) : "l"(a7)); pacc[(w * NB + 7) * 32 + lane] = f;
        __syncthreads();

        // ---- owner tail: reduce 16 k-partials, scale, store alpha_t + partial ----
        if (owner) {
            float ssum = 0.f;
#pragma unroll
            for (int w2 = 0; w2 < NW; w2++) {
                float2 pp = pacc[(w2 * NB + w) * 32 + lane];
                ssum += pp.x + pp.y;
            }
            if (!rz_done) {                 // slow path: s_{t-2} not yet visible
                for (;;) {
                    if (__all_sync(0xffffffffu, (lane >= 20) | (pre != 0.f))) break;
                    if (lane < 20) pre = ld_cg_f32(gp);
                }
                rz = rsqrtf(warp_sum(lane < 20 ? pre : 0.f) * S0F);
            }
            float val = ssum * Bms[lane * BMP + o] * rz;
            float vt = __uint_as_float((__float_as_uint(val) & ~3u) | tag_w);
            st_cg_f32(&g_alpha[curr][b][col], vt);
            float zp = warp_sum(vt);
            if (lane == 0) st_cg_f32(&g_p[t][b][jg], zp);
        }

        // ---- prefetch next step's slice (tags gate staleness) ----
        if (t + 1 < TLEN) ISSUE_SLICE(curr);
    }
#undef ISSUE_SLICE
}

// ---------------- kernel 4a: parallel loglik + regularizer partials ----------------
__global__ void finalize1_kernel(const float* __restrict__ Ag,
                                 const int* __restrict__ rf,
                                 const int* __restrict__ rt) {
    __shared__ double red[256];
    int blk = blockIdx.x, tid = threadIdx.x;
    double acc = 0.0;
    if (blk < 64) {
        int b = blk & 31, t0 = (blk >> 5) * 1024;
        for (int i = tid; i < 1024; i += 256) {
            int t = t0 + i;
            const float4* row = (const float4*)&g_p[t][b][0];  // 20 floats, 16B-aligned
            float4 r0 = row[0], r1 = row[1], r2 = row[2], r3 = row[3], r4 = row[4];
            float s = ((r0.x + r0.y) + (r0.z + r0.w)) + ((r1.x + r1.y) + (r1.z + r1.w))
                    + ((r2.x + r2.y) + (r2.z + r2.w)) + ((r3.x + r3.y) + (r3.z + r3.w))
                    + ((r4.x + r4.y) + (r4.z + r4.w));
            if (t <= TLEN - 3) {
                acc -= (double)logf(rsqrtf(s * S0F));  // divisor applied at step t+2
            } else if (t == TLEN - 1) {
                acc += (double)logf(s);
            }
        }
    } else {
        int idx = (blk - 64) * 256 + tid;
        if (idx < NREG) {
            float a = Ag[(size_t)rf[idx] * S + rt[idx]];
            acc = (double)log1pf(-a);
        }
    }
    red[tid] = acc;
    __syncthreads();
    for (int st = 128; st; st >>= 1) {
        if (tid < st) red[tid] += red[tid + st];
        __syncthreads();
    }
    if (tid == 0) g_part[blk] = red[0];
}

// ---------------- kernel 4b: combine ----------------
__global__ void finalize2_kernel(float* __restrict__ out) {
    if (threadIdx.x == 0) {
        double ll = 0.0, rg = 0.0;
        for (int i = 0; i < 64; i++) ll += g_part[i];
        for (int i = 64; i < 84; i++) rg += g_part[i];
        double loss = -(ll / (double)BATCH) - 4.0 * (rg / (double)NREG);
        out[0] = (float)loss;
    }
}

// ---------------- launcher ----------------
extern "C" void kernel_launch(void* const* d_in, const int* in_sizes, int n_in,
                              void* d_out, int out_size) {
    const float* inputs = (const float*)d_in[0];   // [32,2048,126]
    const float* A      = (const float*)d_in[1];   // [610,610]
    const float* Bm     = (const float*)d_in[2];   // [610,126]
    const float* I      = (const float*)d_in[3];   // [610]
    const int*   rf     = (const int*)d_in[4];     // [5000]
    const int*   rt     = (const int*)d_in[5];     // [5000]
    float* out = (float*)d_out;

    cudaFuncSetAttribute(hmm_kernel,
                         cudaFuncAttributeMaxDynamicSharedMemorySize, SM_BYTES);

    reset_kernel<<<80, 256>>>();
    obs_kernel<<<(BATCH * TLEN) / 8, 256>>>(inputs);
    nop_kernel<<<1, 32>>>();
    dim3 grid(JG, BG);
    hmm_kernel<<<grid, 512, SM_BYTES>>>(A, Bm, I);
    finalize1_kernel<<<84, 256>>>(A, rf, rt);
    finalize2_kernel<<<1, 32>>>(out);
}